// round 12
// baseline (speedup 1.0000x reference)
#include <cuda_runtime.h>
#include <cuda_fp16.h>
#include <cstdint>

// ---------------- problem constants ----------------
#define JB 8
#define JT 256
#define JU 64
#define JD 512
#define JV 1024
#define JM (JB * JT * JU)                 // 131072
#define MAIN_OUT ((long long)JM * JV)     // 134217728

// ---------------- tile config ----------------
#define BM 128
#define BN 128
#define BK 64
#define NCH (JD / BK)          // 8 k-chunks
#define NKK 4                  // k16 steps per chunk

// smem rows: 128B data + 16B pad = 144B (conflict-free STS + LDSM)
#define ROWB 144
#define MATB (128 * ROWB)          // 18432
// A: double-buffered (hi only); B: triple-buffered fp16
#define S_A(s)  ((s) * MATB)
#define O_B(j)  (2 * MATB + (j) * MATB)
#define SMEM_TOT (5 * MATB)        // 92160  -> 2 CTAs per SM

// W as fp16 (device scratch; no allocation)
__device__ __half g_Wf[JV * JD];

// ---------------- helpers ----------------
__device__ __forceinline__ uint32_t smem_u32(const void* p) {
    uint32_t a;
    asm("{ .reg .u64 t; cvta.to.shared.u64 t, %1; cvt.u32.u64 %0, t; }" : "=r"(a) : "l"(p));
    return a;
}
__device__ __forceinline__ void ldsm_x4(uint32_t* r, uint32_t addr) {
    asm volatile("ldmatrix.sync.aligned.m8n8.x4.shared.b16 {%0,%1,%2,%3}, [%4];"
                 : "=r"(r[0]), "=r"(r[1]), "=r"(r[2]), "=r"(r[3]) : "r"(addr));
}
__device__ __forceinline__ void mma16816(float* d, const uint32_t* a, const uint32_t* b) {
    asm volatile(
        "mma.sync.aligned.m16n8k16.row.col.f32.f16.f16.f32 "
        "{%0,%1,%2,%3}, {%4,%5,%6,%7}, {%8,%9}, {%0,%1,%2,%3};"
        : "+f"(d[0]), "+f"(d[1]), "+f"(d[2]), "+f"(d[3])
        : "r"(a[0]), "r"(a[1]), "r"(a[2]), "r"(a[3]), "r"(b[0]), "r"(b[1]));
}
__device__ __forceinline__ void cp16(uint32_t dst, const void* src) {
    asm volatile("cp.async.cg.shared.global [%0], [%1], 16;" :: "r"(dst), "l"(src) : "memory");
}
#define CP_COMMIT() asm volatile("cp.async.commit_group;" ::: "memory")
#define CP_WAIT1()  asm volatile("cp.async.wait_group 1;" ::: "memory")
#define CP_WAIT0()  asm volatile("cp.async.wait_group 0;" ::: "memory")

// ---------------- W convert pre-kernel (+ tail lengths passthrough) ----------------
__global__ void wconv_kernel(const float* __restrict__ W,
                             const int* __restrict__ sl,
                             const int* __restrict__ tl,
                             float* __restrict__ out,
                             int extra)
{
    int i = blockIdx.x * blockDim.x + threadIdx.x;
    if (i < JV * JD) g_Wf[i] = __float2half_rn(W[i]);
    if (blockIdx.x == 0) {
        int t = threadIdx.x;
        if (t < 8 && t < extra)                 out[MAIN_OUT + t] = (float)sl[t];
        else if (t >= 8 && t < 16 && t < extra) out[MAIN_OUT + t] = (float)tl[t - 8];
    }
}

// ---------------- main HMMA GEMM: 256 thr, 8 warps (2M x 4N), warp 64x32, fp16 1-pass ----------------
__global__ __launch_bounds__(256, 2)
void joiner_mma_kernel(const float* __restrict__ src,   // [B,T,D]
                       const float* __restrict__ tgt,   // [B,U,D]
                       const float* __restrict__ bias,  // [V]
                       float* __restrict__ out)         // [M,V]
{
    extern __shared__ char smem[];
    const uint32_t sb = smem_u32(smem);
    const int tid = threadIdx.x;
    const int wid = tid >> 5;
    const int lid = tid & 31;
    const int mw  = wid >> 2;      // 0..1 -> 64-row half
    const int nw  = wid & 3;       // 0..3 -> 32-col quarter

    const int n0 = blockIdx.x * BN;
    const int m0 = blockIdx.y * BM;
    const int bidx = m0 / (JT * JU);
    const int t0 = (m0 % (JT * JU)) / JU;     // tile spans t0, t0+1

    // ---- A producer geometry: thread -> row ar (0..127), 32-col half ag ----
    const int ar = tid >> 1;
    const int ag = tid & 1;
    const float* srcP = src + (size_t)bidx * JT * JD + (size_t)(t0 + (ar >> 6)) * JD + ag * 32;
    const float* tgtP = tgt + (size_t)bidx * JU * JD + (size_t)(ar & 63) * JD + ag * 32;
    const uint32_t aSts = (uint32_t)(ar * ROWB + ag * 64);

    // ---- B producer geometry: thread -> row br (0..127), 32-col half bg ----
    const int br = tid >> 1;
    const int bg = tid & 1;
    const __half* wP = g_Wf + (size_t)(n0 + br) * JD + bg * 32;
    const uint32_t bSts = (uint32_t)(br * ROWB + bg * 64);

    float acc[4][4][4];
#pragma unroll
    for (int mt = 0; mt < 4; mt++)
#pragma unroll
        for (int nt = 0; nt < 4; nt++)
#pragma unroll
            for (int j = 0; j < 4; j++) acc[mt][nt][j] = 0.0f;

    // ldmatrix lane offsets
    const uint32_t aLane = (uint32_t)((lid & 15) * ROWB + (lid >> 4) * 16);
    const uint32_t bLane = (uint32_t)((lid & 7) * ROWB + ((lid >> 3) & 1) * 16 + (lid >> 4) * (8 * ROWB));

    // ---- A produce (relu(src+tgt) -> fp16) into stage s for k-chunk base k0 ----
    auto produceA = [&](int k0, int s) {
        const float4* sp = (const float4*)(srcP + k0);
        const float4* tp = (const float4*)(tgtP + k0);
#pragma unroll
        for (int q = 0; q < 4; q++) {
            const float4 s0 = sp[2 * q], s1 = sp[2 * q + 1];
            const float4 u0 = tp[2 * q], u1 = tp[2 * q + 1];
            __half2 p0 = __floats2half2_rn(fmaxf(s0.x + u0.x, 0.f), fmaxf(s0.y + u0.y, 0.f));
            __half2 p1 = __floats2half2_rn(fmaxf(s0.z + u0.z, 0.f), fmaxf(s0.w + u0.w, 0.f));
            __half2 p2 = __floats2half2_rn(fmaxf(s1.x + u1.x, 0.f), fmaxf(s1.y + u1.y, 0.f));
            __half2 p3 = __floats2half2_rn(fmaxf(s1.z + u1.z, 0.f), fmaxf(s1.w + u1.w, 0.f));
            uint4 hv;
            hv.x = *reinterpret_cast<uint32_t*>(&p0);
            hv.y = *reinterpret_cast<uint32_t*>(&p1);
            hv.z = *reinterpret_cast<uint32_t*>(&p2);
            hv.w = *reinterpret_cast<uint32_t*>(&p3);
            *(uint4*)(smem + S_A(s) + aSts + q * 16) = hv;
        }
    };

    // ---- prologue: cp.async B0, B1; produce A0 ----
#pragma unroll
    for (int j = 0; j < 4; j++) cp16(sb + O_B(0) + bSts + j * 16, wP + j * 8);
    CP_COMMIT();
#pragma unroll
    for (int j = 0; j < 4; j++) cp16(sb + O_B(1) + bSts + j * 16, wP + BK + j * 8);
    CP_COMMIT();
    produceA(0, 0);
    CP_WAIT1();
    __syncthreads();

    const int prodKK = wid & 3;    // stagger producer stalls across warps

    for (int c = 0; c < NCH; c++) {
        const int sA = c & 1;
        const bool more = (c + 1 < NCH);

        // issue B(c+2) two chunks ahead
        if (c + 2 < NCH) {
            const int k2 = (c + 2) * BK;
            const uint32_t bo = O_B((c + 2) % 3);
#pragma unroll
            for (int j = 0; j < 4; j++) cp16(sb + bo + bSts + j * 16, wP + k2 + j * 8);
            CP_COMMIT();
        }

        const uint32_t aB = sb + S_A(sA) + (uint32_t)(mw * 64 * ROWB) + aLane;
        const uint32_t bB = sb + O_B(c % 3) + (uint32_t)(nw * 32 * ROWB) + bLane;

#pragma unroll
        for (int kk = 0; kk < NKK; kk++) {
            uint32_t a[4][4], b[8];
#pragma unroll
            for (int mt = 0; mt < 4; mt++) ldsm_x4(a[mt], aB + mt * 16 * ROWB + kk * 32);
#pragma unroll
            for (int p = 0; p < 2; p++) ldsm_x4(&b[p * 4], bB + p * 16 * ROWB + kk * 32);
#pragma unroll
            for (int mt = 0; mt < 4; mt++)
#pragma unroll
                for (int nt = 0; nt < 4; nt++) mma16816(acc[mt][nt], a[mt], &b[nt * 2]);

            if (more && kk == prodKK) produceA((c + 1) * BK, sA ^ 1);
        }

        if (more) {
            if (c + 2 < NCH) CP_WAIT1(); else CP_WAIT0();
            __syncthreads();
        }
    }

    // ---- epilogue: bias + store ----
    const int wn0 = n0 + nw * 32;
    float2 bv[4];
#pragma unroll
    for (int nt = 0; nt < 4; nt++)
        bv[nt] = *(const float2*)(bias + wn0 + nt * 8 + (lid & 3) * 2);

#pragma unroll
    for (int mt = 0; mt < 4; mt++) {
        const int r0 = m0 + mw * 64 + mt * 16 + (lid >> 2);
        float* p0 = out + (size_t)r0 * JV + wn0 + (lid & 3) * 2;
        float* p1 = p0 + (size_t)8 * JV;
#pragma unroll
        for (int nt = 0; nt < 4; nt++) {
            float2 o0, o1;
            o0.x = acc[mt][nt][0] + bv[nt].x;
            o0.y = acc[mt][nt][1] + bv[nt].y;
            o1.x = acc[mt][nt][2] + bv[nt].x;
            o1.y = acc[mt][nt][3] + bv[nt].y;
            *(float2*)(p0 + nt * 8) = o0;
            *(float2*)(p1 + nt * 8) = o1;
        }
    }
}

extern "C" void kernel_launch(void* const* d_in, const int* in_sizes, int n_in,
                              void* d_out, int out_size)
{
    const float* src  = (const float*)d_in[0];
    const int*   sl   = (const int*)  d_in[1];
    const float* tgt  = (const float*)d_in[2];
    const int*   tl   = (const int*)  d_in[3];
    const float* W    = (const float*)d_in[4];
    const float* bias = (const float*)d_in[5];
    float* out = (float*)d_out;

    const long long extra = (long long)out_size - MAIN_OUT;

    wconv_kernel<<<(JV * JD + 255) / 256, 256>>>(W, sl, tl, out,
                                                 extra > 0 ? (int)extra : 0);

    cudaFuncSetAttribute(joiner_mma_kernel,
                         cudaFuncAttributeMaxDynamicSharedMemorySize, SMEM_TOT);
    dim3 grid(JV / BN, JM / BM);   // (8, 1024)
    joiner_mma_kernel<<<grid, 256, SMEM_TOT>>>(src, tgt, bias, out);
}

// round 13
// speedup vs baseline: 1.4107x; 1.4107x over previous
#include <cuda_runtime.h>
#include <cuda_fp16.h>
#include <cstdint>

// ---------------- problem constants ----------------
#define JB 8
#define JT 256
#define JU 64
#define JD 512
#define JV 1024
#define JM (JB * JT * JU)                 // 131072
#define MAIN_OUT ((long long)JM * JV)     // 134217728

// ---------------- tile config ----------------
#define BM 128
#define BN 256
#define BK 64
#define NCH (JD / BK)          // 8 k-chunks
#define NKK 4                  // k16 steps per chunk

// smem rows: 128B data + 16B pad = 144B (conflict-free STS + LDSM)
#define ROWB 144
#define AMATB (128 * ROWB)         // 18432
#define BMATB (256 * ROWB)         // 36864
// A: double-buffered; B: triple-buffered (fp16)
#define S_A(s)  ((s) * AMATB)
#define O_B(j)  (2 * AMATB + (j) * BMATB)
#define SMEM_TOT (2 * AMATB + 3 * BMATB)   // 147456 -> 1 CTA/SM

// W as fp16 (device scratch; no allocation)
__device__ __half g_Wf[JV * JD];

// ---------------- helpers ----------------
__device__ __forceinline__ uint32_t smem_u32(const void* p) {
    uint32_t a;
    asm("{ .reg .u64 t; cvta.to.shared.u64 t, %1; cvt.u32.u64 %0, t; }" : "=r"(a) : "l"(p));
    return a;
}
__device__ __forceinline__ void ldsm_x4(uint32_t* r, uint32_t addr) {
    asm volatile("ldmatrix.sync.aligned.m8n8.x4.shared.b16 {%0,%1,%2,%3}, [%4];"
                 : "=r"(r[0]), "=r"(r[1]), "=r"(r[2]), "=r"(r[3]) : "r"(addr));
}
__device__ __forceinline__ void mma16816(float* d, const uint32_t* a, const uint32_t* b) {
    asm volatile(
        "mma.sync.aligned.m16n8k16.row.col.f32.f16.f16.f32 "
        "{%0,%1,%2,%3}, {%4,%5,%6,%7}, {%8,%9}, {%0,%1,%2,%3};"
        : "+f"(d[0]), "+f"(d[1]), "+f"(d[2]), "+f"(d[3])
        : "r"(a[0]), "r"(a[1]), "r"(a[2]), "r"(a[3]), "r"(b[0]), "r"(b[1]));
}
__device__ __forceinline__ void cp16(uint32_t dst, const void* src) {
    asm volatile("cp.async.cg.shared.global [%0], [%1], 16;" :: "r"(dst), "l"(src) : "memory");
}
#define CP_COMMIT() asm volatile("cp.async.commit_group;" ::: "memory")
#define CP_WAIT1()  asm volatile("cp.async.wait_group 1;" ::: "memory")
#define CP_WAIT0()  asm volatile("cp.async.wait_group 0;" ::: "memory")

// ---------------- W convert pre-kernel (+ tail lengths passthrough) ----------------
__global__ void wconv_kernel(const float* __restrict__ W,
                             const int* __restrict__ sl,
                             const int* __restrict__ tl,
                             float* __restrict__ out,
                             int extra)
{
    int i = blockIdx.x * blockDim.x + threadIdx.x;
    if (i < JV * JD) g_Wf[i] = __float2half_rn(W[i]);
    if (blockIdx.x == 0) {
        int t = threadIdx.x;
        if (t < 8 && t < extra)                 out[MAIN_OUT + t] = (float)sl[t];
        else if (t >= 8 && t < 16 && t < extra) out[MAIN_OUT + t] = (float)tl[t - 8];
    }
}

// ---------------- main HMMA GEMM: 256 thr, 8 warps (2M x 4N), warp 64x64, fp16 1-pass ----------------
__global__ __launch_bounds__(256, 1)
void joiner_mma_kernel(const float* __restrict__ src,   // [B,T,D]
                       const float* __restrict__ tgt,   // [B,U,D]
                       const float* __restrict__ bias,  // [V]
                       float* __restrict__ out)         // [M,V]
{
    extern __shared__ char smem[];
    const uint32_t sb = smem_u32(smem);
    const int tid = threadIdx.x;
    const int wid = tid >> 5;
    const int lid = tid & 31;
    const int mw  = wid >> 2;      // 0..1 -> 64-row half
    const int nw  = wid & 3;       // 0..3 -> 64-col quarter

    const int n0 = blockIdx.x * BN;
    const int m0 = blockIdx.y * BM;
    const int bidx = m0 / (JT * JU);
    const int t0 = (m0 % (JT * JU)) / JU;     // tile spans t0, t0+1

    // ---- A producer geometry: thread -> u row (0..63), 16-float seg ag (0..3) ----
    // Each thread builds A rows u (t=t0) and 64+u (t=t0+1) for its 16 cols.
    const int au = tid >> 2;
    const int ag = tid & 3;
    const float* srcP0 = src + (size_t)bidx * JT * JD + (size_t)t0 * JD + ag * 16;
    const float* srcP1 = srcP0 + JD;
    const float* tgtP  = tgt + (size_t)bidx * JU * JD + (size_t)au * JD + ag * 16;
    const uint32_t aSts0 = (uint32_t)(au * ROWB + ag * 32);
    const uint32_t aSts1 = (uint32_t)((64 + au) * ROWB + ag * 32);

    // ---- B producer geometry: thread -> row br (0..255), full 128B row per chunk ----
    const __half* wP = g_Wf + (size_t)(n0 + tid) * JD;
    const uint32_t bSts = (uint32_t)(tid * ROWB);

    float acc[4][8][4];
#pragma unroll
    for (int mt = 0; mt < 4; mt++)
#pragma unroll
        for (int nt = 0; nt < 8; nt++)
#pragma unroll
            for (int j = 0; j < 4; j++) acc[mt][nt][j] = 0.0f;

    // ldmatrix lane offsets
    const uint32_t aLane = (uint32_t)((lid & 15) * ROWB + (lid >> 4) * 16);
    const uint32_t bLane = (uint32_t)((lid & 7) * ROWB + ((lid >> 3) & 1) * 16 + (lid >> 4) * (8 * ROWB));

    // ---- A produce: relu(src+tgt) -> fp16, both t rows from one tgt read ----
    auto produceA = [&](int k0, int s) {
        const float4* tp  = (const float4*)(tgtP + k0);
        const float4* sp0 = (const float4*)(srcP0 + k0);
        const float4* sp1 = (const float4*)(srcP1 + k0);
        float4 tv[4], s0[4], s1[4];
#pragma unroll
        for (int q = 0; q < 4; q++) { tv[q] = tp[q]; s0[q] = sp0[q]; s1[q] = sp1[q]; }
        uint4 h0[2], h1[2];
#pragma unroll
        for (int h = 0; h < 2; h++) {
#pragma unroll
            for (int q = 0; q < 2; q++) {
                const float4 a = s0[h * 2 + q], b = s1[h * 2 + q], t = tv[h * 2 + q];
                __half2 p0 = __floats2half2_rn(fmaxf(a.x + t.x, 0.f), fmaxf(a.y + t.y, 0.f));
                __half2 p1 = __floats2half2_rn(fmaxf(a.z + t.z, 0.f), fmaxf(a.w + t.w, 0.f));
                __half2 q0 = __floats2half2_rn(fmaxf(b.x + t.x, 0.f), fmaxf(b.y + t.y, 0.f));
                __half2 q1 = __floats2half2_rn(fmaxf(b.z + t.z, 0.f), fmaxf(b.w + t.w, 0.f));
                ((uint32_t*)&h0[h])[q * 2 + 0] = *reinterpret_cast<uint32_t*>(&p0);
                ((uint32_t*)&h0[h])[q * 2 + 1] = *reinterpret_cast<uint32_t*>(&p1);
                ((uint32_t*)&h1[h])[q * 2 + 0] = *reinterpret_cast<uint32_t*>(&q0);
                ((uint32_t*)&h1[h])[q * 2 + 1] = *reinterpret_cast<uint32_t*>(&q1);
            }
        }
        *(uint4*)(smem + S_A(s) + aSts0)      = h0[0];
        *(uint4*)(smem + S_A(s) + aSts0 + 16) = h0[1];
        *(uint4*)(smem + S_A(s) + aSts1)      = h1[0];
        *(uint4*)(smem + S_A(s) + aSts1 + 16) = h1[1];
    };

    // ---- prologue: cp.async B0, B1; produce A0 ----
#pragma unroll
    for (int j = 0; j < 8; j++) cp16(sb + O_B(0) + bSts + j * 16, wP + j * 8);
    CP_COMMIT();
#pragma unroll
    for (int j = 0; j < 8; j++) cp16(sb + O_B(1) + bSts + j * 16, wP + BK + j * 8);
    CP_COMMIT();
    produceA(0, 0);
    CP_WAIT1();
    __syncthreads();

    const int prodKK = wid & 3;    // stagger producer stalls across warps

    for (int c = 0; c < NCH; c++) {
        const int sA = c & 1;
        const bool more = (c + 1 < NCH);

        // issue B(c+2) two chunks ahead
        if (c + 2 < NCH) {
            const int k2 = (c + 2) * BK;
            const uint32_t bo = O_B((c + 2) % 3);
#pragma unroll
            for (int j = 0; j < 8; j++) cp16(sb + bo + bSts + j * 16, wP + k2 + j * 8);
            CP_COMMIT();
        }

        const uint32_t aB = sb + S_A(sA) + (uint32_t)(mw * 64 * ROWB) + aLane;
        const uint32_t bB = sb + O_B(c % 3) + (uint32_t)(nw * 64 * ROWB) + bLane;

#pragma unroll
        for (int kk = 0; kk < NKK; kk++) {
            uint32_t a[4][4], b[16];
#pragma unroll
            for (int mt = 0; mt < 4; mt++) ldsm_x4(a[mt], aB + mt * 16 * ROWB + kk * 32);
#pragma unroll
            for (int p = 0; p < 4; p++) ldsm_x4(&b[p * 4], bB + p * 16 * ROWB + kk * 32);
#pragma unroll
            for (int mt = 0; mt < 4; mt++)
#pragma unroll
                for (int nt = 0; nt < 8; nt++) mma16816(acc[mt][nt], a[mt], &b[nt * 2]);

            if (more && kk == prodKK) produceA((c + 1) * BK, sA ^ 1);
        }

        if (more) {
            if (c + 2 < NCH) CP_WAIT1(); else CP_WAIT0();
            __syncthreads();
        }
    }

    // ---- epilogue: bias + store ----
    const int wn0 = n0 + nw * 64;
    float2 bv[8];
#pragma unroll
    for (int nt = 0; nt < 8; nt++)
        bv[nt] = *(const float2*)(bias + wn0 + nt * 8 + (lid & 3) * 2);

#pragma unroll
    for (int mt = 0; mt < 4; mt++) {
        const int r0 = m0 + mw * 64 + mt * 16 + (lid >> 2);
        float* p0 = out + (size_t)r0 * JV + wn0 + (lid & 3) * 2;
        float* p1 = p0 + (size_t)8 * JV;
#pragma unroll
        for (int nt = 0; nt < 8; nt++) {
            float2 o0, o1;
            o0.x = acc[mt][nt][0] + bv[nt].x;
            o0.y = acc[mt][nt][1] + bv[nt].y;
            o1.x = acc[mt][nt][2] + bv[nt].x;
            o1.y = acc[mt][nt][3] + bv[nt].y;
            *(float2*)(p0 + nt * 8) = o0;
            *(float2*)(p1 + nt * 8) = o1;
        }
    }
}

extern "C" void kernel_launch(void* const* d_in, const int* in_sizes, int n_in,
                              void* d_out, int out_size)
{
    const float* src  = (const float*)d_in[0];
    const int*   sl   = (const int*)  d_in[1];
    const float* tgt  = (const float*)d_in[2];
    const int*   tl   = (const int*)  d_in[3];
    const float* W    = (const float*)d_in[4];
    const float* bias = (const float*)d_in[5];
    float* out = (float*)d_out;

    const long long extra = (long long)out_size - MAIN_OUT;

    wconv_kernel<<<(JV * JD + 255) / 256, 256>>>(W, sl, tl, out,
                                                 extra > 0 ? (int)extra : 0);

    cudaFuncSetAttribute(joiner_mma_kernel,
                         cudaFuncAttributeMaxDynamicSharedMemorySize, SMEM_TOT);
    dim3 grid(JV / BN, JM / BM);   // (4, 1024)
    joiner_mma_kernel<<<grid, 256, SMEM_TOT>>>(src, tgt, bias, out);
}

// round 14
// speedup vs baseline: 1.4409x; 1.0214x over previous
#include <cuda_runtime.h>
#include <cuda_fp16.h>
#include <cstdint>

// ---------------- problem constants ----------------
#define JB 8
#define JT 256
#define JU 64
#define JD 512
#define JV 1024
#define JM (JB * JT * JU)                 // 131072
#define MAIN_OUT ((long long)JM * JV)     // 134217728

// ---------------- tile config ----------------
#define BM 128
#define BN 256
#define BK 64
#define NCH (JD / BK)          // 8 k-chunks
#define NKK 4                  // k16 steps per chunk

// smem rows: 128B data + 16B pad = 144B (conflict-free STS + LDSM)
#define ROWB 144
#define AMATB (128 * ROWB)         // 18432
#define BMATB (256 * ROWB)         // 36864
// A: double-buffered; B: triple-buffered (fp16)
#define S_A(s)  ((s) * AMATB)
#define O_B(j)  (2 * AMATB + (j) * BMATB)
#define SMEM_TOT (2 * AMATB + 3 * BMATB)   // 147456 -> 1 CTA/SM

// W as fp16 (device scratch; no allocation)
__device__ __half g_Wf[JV * JD];

// ---------------- helpers ----------------
__device__ __forceinline__ uint32_t smem_u32(const void* p) {
    uint32_t a;
    asm("{ .reg .u64 t; cvta.to.shared.u64 t, %1; cvt.u32.u64 %0, t; }" : "=r"(a) : "l"(p));
    return a;
}
__device__ __forceinline__ void ldsm_x4(uint32_t* r, uint32_t addr) {
    asm volatile("ldmatrix.sync.aligned.m8n8.x4.shared.b16 {%0,%1,%2,%3}, [%4];"
                 : "=r"(r[0]), "=r"(r[1]), "=r"(r[2]), "=r"(r[3]) : "r"(addr));
}
__device__ __forceinline__ void mma16816(float* d, const uint32_t* a, const uint32_t* b) {
    asm volatile(
        "mma.sync.aligned.m16n8k16.row.col.f32.f16.f16.f32 "
        "{%0,%1,%2,%3}, {%4,%5,%6,%7}, {%8,%9}, {%0,%1,%2,%3};"
        : "+f"(d[0]), "+f"(d[1]), "+f"(d[2]), "+f"(d[3])
        : "r"(a[0]), "r"(a[1]), "r"(a[2]), "r"(a[3]), "r"(b[0]), "r"(b[1]));
}
__device__ __forceinline__ void cp16(uint32_t dst, const void* src) {
    asm volatile("cp.async.cg.shared.global [%0], [%1], 16;" :: "r"(dst), "l"(src) : "memory");
}
#define CP_COMMIT() asm volatile("cp.async.commit_group;" ::: "memory")
#define CP_WAIT1()  asm volatile("cp.async.wait_group 1;" ::: "memory")
#define CP_WAIT0()  asm volatile("cp.async.wait_group 0;" ::: "memory")

// ---------------- W convert pre-kernel (+ tail lengths passthrough) ----------------
__global__ void wconv_kernel(const float* __restrict__ W,
                             const int* __restrict__ sl,
                             const int* __restrict__ tl,
                             float* __restrict__ out,
                             int extra)
{
    int i = blockIdx.x * blockDim.x + threadIdx.x;
    if (i < JV * JD) g_Wf[i] = __float2half_rn(W[i]);
    if (blockIdx.x == 0) {
        int t = threadIdx.x;
        if (t < 8 && t < extra)                 out[MAIN_OUT + t] = (float)sl[t];
        else if (t >= 8 && t < 16 && t < extra) out[MAIN_OUT + t] = (float)tl[t - 8];
    }
}

// ---------------- main HMMA GEMM: 256 thr, 8 warps (2M x 4N), warp 64x64, fp16 1-pass ----------------
__global__ __launch_bounds__(256)
void joiner_mma_kernel(const float* __restrict__ src,   // [B,T,D]
                       const float* __restrict__ tgt,   // [B,U,D]
                       const float* __restrict__ bias,  // [V]
                       float* __restrict__ out)         // [M,V]
{
    extern __shared__ char smem[];
    const uint32_t sb = smem_u32(smem);
    const int tid = threadIdx.x;
    const int wid = tid >> 5;
    const int lid = tid & 31;
    const int mw  = wid >> 2;      // 0..1 -> 64-row half
    const int nw  = wid & 3;       // 0..3 -> 64-col quarter

    const int n0 = blockIdx.x * BN;
    const int m0 = blockIdx.y * BM;
    const int bidx = m0 / (JT * JU);
    const int t0 = (m0 % (JT * JU)) / JU;     // tile spans t0, t0+1

    // ---- A producer geometry: thread -> u row (0..63), 16-float seg ag (0..3) ----
    const int au = tid >> 2;
    const int ag = tid & 3;
    const float* srcP0 = src + (size_t)bidx * JT * JD + (size_t)t0 * JD + ag * 16;
    const float* srcP1 = srcP0 + JD;
    const float* tgtP  = tgt + (size_t)bidx * JU * JD + (size_t)au * JD + ag * 16;
    const uint32_t aSts0 = (uint32_t)(au * ROWB + ag * 32);
    const uint32_t aSts1 = (uint32_t)((64 + au) * ROWB + ag * 32);

    // ---- B producer geometry: thread -> row (0..255), full 128B row per chunk ----
    const __half* wP = g_Wf + (size_t)(n0 + tid) * JD;
    const uint32_t bSts = (uint32_t)(tid * ROWB);

    float acc[4][8][4];
#pragma unroll
    for (int mt = 0; mt < 4; mt++)
#pragma unroll
        for (int nt = 0; nt < 8; nt++)
#pragma unroll
            for (int j = 0; j < 4; j++) acc[mt][nt][j] = 0.0f;

    // ldmatrix lane offsets
    const uint32_t aLane = (uint32_t)((lid & 15) * ROWB + (lid >> 4) * 16);
    const uint32_t bLane = (uint32_t)((lid & 7) * ROWB + ((lid >> 3) & 1) * 16 + (lid >> 4) * (8 * ROWB));

    // ---- A produce pieces ----
    // convert + STS using prefetched tgt values; src rows are L1-hot (broadcast)
    auto convStoreA = [&](int k0, int s, const float4* tv) {
        const float4* sp0 = (const float4*)(srcP0 + k0);
        const float4* sp1 = (const float4*)(srcP1 + k0);
#pragma unroll
        for (int h = 0; h < 2; h++) {
            uint4 h0, h1;
#pragma unroll
            for (int q = 0; q < 2; q++) {
                const float4 a = sp0[h * 2 + q], b = sp1[h * 2 + q], t = tv[h * 2 + q];
                __half2 p0 = __floats2half2_rn(fmaxf(a.x + t.x, 0.f), fmaxf(a.y + t.y, 0.f));
                __half2 p1 = __floats2half2_rn(fmaxf(a.z + t.z, 0.f), fmaxf(a.w + t.w, 0.f));
                __half2 q0 = __floats2half2_rn(fmaxf(b.x + t.x, 0.f), fmaxf(b.y + t.y, 0.f));
                __half2 q1 = __floats2half2_rn(fmaxf(b.z + t.z, 0.f), fmaxf(b.w + t.w, 0.f));
                ((uint32_t*)&h0)[q * 2 + 0] = *reinterpret_cast<uint32_t*>(&p0);
                ((uint32_t*)&h0)[q * 2 + 1] = *reinterpret_cast<uint32_t*>(&p1);
                ((uint32_t*)&h1)[q * 2 + 0] = *reinterpret_cast<uint32_t*>(&q0);
                ((uint32_t*)&h1)[q * 2 + 1] = *reinterpret_cast<uint32_t*>(&q1);
            }
            *(uint4*)(smem + S_A(s) + aSts0 + h * 16) = h0;
            *(uint4*)(smem + S_A(s) + aSts1 + h * 16) = h1;
        }
    };

    // ---- prologue: cp.async B0, B1; produce A0 (tgt loaded inline) ----
#pragma unroll
    for (int j = 0; j < 8; j++) cp16(sb + O_B(0) + bSts + j * 16, wP + j * 8);
    CP_COMMIT();
#pragma unroll
    for (int j = 0; j < 8; j++) cp16(sb + O_B(1) + bSts + j * 16, wP + BK + j * 8);
    CP_COMMIT();
    {
        float4 tv[4];
        const float4* tp = (const float4*)(tgtP);
#pragma unroll
        for (int q = 0; q < 4; q++) tv[q] = tp[q];
        convStoreA(0, 0, tv);
    }
    CP_WAIT1();
    __syncthreads();

    // stagger produce so SMSP-paired warps (wid, wid+4) hit different k-steps
    const int prodKK = ((wid & 3) + (wid >> 2) * 2) & 3;

    for (int c = 0; c < NCH; c++) {
        const int sA = c & 1;
        const bool more = (c + 1 < NCH);

        // prefetch tgt rows for chunk c+1 (long-latency; lands during MMAs)
        float4 tv[4];
        if (more) {
            const float4* tp = (const float4*)(tgtP + (c + 1) * BK);
#pragma unroll
            for (int q = 0; q < 4; q++) tv[q] = tp[q];
        }

        // issue B(c+2) two chunks ahead
        if (c + 2 < NCH) {
            const int k2 = (c + 2) * BK;
            const uint32_t bo = O_B((c + 2) % 3);
#pragma unroll
            for (int j = 0; j < 8; j++) cp16(sb + bo + bSts + j * 16, wP + k2 + j * 8);
            CP_COMMIT();
        }

        const uint32_t aB = sb + S_A(sA) + (uint32_t)(mw * 64 * ROWB) + aLane;
        const uint32_t bB = sb + O_B(c % 3) + (uint32_t)(nw * 64 * ROWB) + bLane;

        // ---- software-pipelined fragment loop ----
        uint32_t a[2][4][4], b[2][16];
#pragma unroll
        for (int mt = 0; mt < 4; mt++) ldsm_x4(a[0][mt], aB + mt * 16 * ROWB);
#pragma unroll
        for (int p = 0; p < 4; p++) ldsm_x4(&b[0][p * 4], bB + p * 16 * ROWB);

#pragma unroll
        for (int kk = 0; kk < NKK; kk++) {
            const int cur = kk & 1;
            const int nxt = cur ^ 1;
            if (kk + 1 < NKK) {
#pragma unroll
                for (int mt = 0; mt < 4; mt++) ldsm_x4(a[nxt][mt], aB + mt * 16 * ROWB + (kk + 1) * 32);
#pragma unroll
                for (int p = 0; p < 4; p++) ldsm_x4(&b[nxt][p * 4], bB + p * 16 * ROWB + (kk + 1) * 32);
            }
#pragma unroll
            for (int mt = 0; mt < 4; mt++)
#pragma unroll
                for (int nt = 0; nt < 8; nt++) mma16816(acc[mt][nt], a[cur][mt], &b[cur][nt * 2]);

            if (more && kk == prodKK) convStoreA((c + 1) * BK, sA ^ 1, tv);
        }

        if (more) {
            if (c + 2 < NCH) CP_WAIT1(); else CP_WAIT0();
            __syncthreads();
        }
    }

    // ---- epilogue: bias + store ----
    const int wn0 = n0 + nw * 64;
    float2 bv[8];
#pragma unroll
    for (int nt = 0; nt < 8; nt++)
        bv[nt] = *(const float2*)(bias + wn0 + nt * 8 + (lid & 3) * 2);

#pragma unroll
    for (int mt = 0; mt < 4; mt++) {
        const int r0 = m0 + mw * 64 + mt * 16 + (lid >> 2);
        float* p0 = out + (size_t)r0 * JV + wn0 + (lid & 3) * 2;
        float* p1 = p0 + (size_t)8 * JV;
#pragma unroll
        for (int nt = 0; nt < 8; nt++) {
            float2 o0, o1;
            o0.x = acc[mt][nt][0] + bv[nt].x;
            o0.y = acc[mt][nt][1] + bv[nt].y;
            o1.x = acc[mt][nt][2] + bv[nt].x;
            o1.y = acc[mt][nt][3] + bv[nt].y;
            *(float2*)(p0 + nt * 8) = o0;
            *(float2*)(p1 + nt * 8) = o1;
        }
    }
}

extern "C" void kernel_launch(void* const* d_in, const int* in_sizes, int n_in,
                              void* d_out, int out_size)
{
    const float* src  = (const float*)d_in[0];
    const int*   sl   = (const int*)  d_in[1];
    const float* tgt  = (const float*)d_in[2];
    const int*   tl   = (const int*)  d_in[3];
    const float* W    = (const float*)d_in[4];
    const float* bias = (const float*)d_in[5];
    float* out = (float*)d_out;

    const long long extra = (long long)out_size - MAIN_OUT;

    wconv_kernel<<<(JV * JD + 255) / 256, 256>>>(W, sl, tl, out,
                                                 extra > 0 ? (int)extra : 0);

    cudaFuncSetAttribute(joiner_mma_kernel,
                         cudaFuncAttributeMaxDynamicSharedMemorySize, SMEM_TOT);
    dim3 grid(JV / BN, JM / BM);   // (4, 1024)
    joiner_mma_kernel<<<grid, 256, SMEM_TOT>>>(src, tgt, bias, out);
}